// round 2
// baseline (speedup 1.0000x reference)
#include <cuda_runtime.h>
#include <cuda_bf16.h>
#include <cstdint>

// Problem shapes (fixed by the reference):
//   node_emb:    [65536, 64] f32   (d_in[0])
//   feature_emb: [512, 64]   f32   (d_in[1])
//   W:           [1, 128]    f32   (d_in[2])  (w_node = W[0:64], w_feat = W[64:128])
//   b:           [1]         f32   (d_in[3])
//   out:         [65536, 512] f32 = node_proj[i] + feat_proj[j] + b

#define BS 65536
#define NF 512
#define D  64

// Scratch for feat_proj + b (allocation-free rule: __device__ global).
__device__ float g_feat[NF];

// ---------------------------------------------------------------------------
// Kernel A: feat_proj[j] = feature_emb[j,:] . W[64:128] + b
// warp-per-row, 512 rows -> 512 warps = 64 blocks x 256 threads
// ---------------------------------------------------------------------------
__global__ __launch_bounds__(256) void feat_kernel(
    const float* __restrict__ feature_emb,
    const float* __restrict__ W,
    const float* __restrict__ b)
{
    const int warp = (blockIdx.x * 256 + threadIdx.x) >> 5;
    const int lane = threadIdx.x & 31;
    if (warp >= NF) return;

    // Each lane covers 2 consecutive elements of the 64-length dot.
    const float2 v = reinterpret_cast<const float2*>(feature_emb)[warp * 32 + lane];
    const float2 w = reinterpret_cast<const float2*>(W)[32 + lane];  // W[64 + 2*lane ..]
    float p = fmaf(v.x, w.x, v.y * w.y);

    #pragma unroll
    for (int off = 16; off > 0; off >>= 1)
        p += __shfl_xor_sync(0xffffffffu, p, off);

    if (lane == 0)
        g_feat[warp] = p + b[0];
}

// ---------------------------------------------------------------------------
// Kernel B: out[row, :] = (node_emb[row,:] . W[0:64]) + g_feat[:]
// warp-per-row. Stores interleaved (lane + 32*q) so each STG.128 warp
// instruction writes 512 contiguous bytes.
// ---------------------------------------------------------------------------
__global__ __launch_bounds__(256) void edge_head_kernel(
    const float* __restrict__ node_emb,
    const float* __restrict__ W,
    float* __restrict__ out)
{
    const int warp = (blockIdx.x * 256 + threadIdx.x) >> 5;   // row index, 0..65535
    const int lane = threadIdx.x & 31;

    // Per-lane feat values for the interleaved store pattern: element
    // out[row, 4*(q*32+lane) .. +3] gets g_feat[4*(q*32+lane) .. +3].
    const float4* f4 = reinterpret_cast<const float4*>(g_feat);
    const float4 f0 = f4[      lane];
    const float4 f1 = f4[ 32 + lane];
    const float4 f2 = f4[ 64 + lane];
    const float4 f3 = f4[ 96 + lane];

    // Dot product: fully coalesced float2 per lane.
    const float2 v = reinterpret_cast<const float2*>(node_emb)[warp * 32 + lane];
    const float2 w = reinterpret_cast<const float2*>(W)[lane];        // W[2*lane ..]
    float p = fmaf(v.x, w.x, v.y * w.y);

    #pragma unroll
    for (int off = 16; off > 0; off >>= 1)
        p += __shfl_xor_sync(0xffffffffu, p, off);   // all lanes now hold the full sum

    float4* o4 = reinterpret_cast<float4*>(out + (size_t)warp * NF);
    float4 r;
    r.x = f0.x + p; r.y = f0.y + p; r.z = f0.z + p; r.w = f0.w + p;
    o4[      lane] = r;
    r.x = f1.x + p; r.y = f1.y + p; r.z = f1.z + p; r.w = f1.w + p;
    o4[ 32 + lane] = r;
    r.x = f2.x + p; r.y = f2.y + p; r.z = f2.z + p; r.w = f2.w + p;
    o4[ 64 + lane] = r;
    r.x = f3.x + p; r.y = f3.y + p; r.z = f3.z + p; r.w = f3.w + p;
    o4[ 96 + lane] = r;
}

// ---------------------------------------------------------------------------
extern "C" void kernel_launch(void* const* d_in, const int* in_sizes, int n_in,
                              void* d_out, int out_size)
{
    const float* node_emb    = (const float*)d_in[0];
    const float* feature_emb = (const float*)d_in[1];
    const float* W           = (const float*)d_in[2];
    const float* b           = (const float*)d_in[3];
    float*       out         = (float*)d_out;

    // Kernel A: 512 warps -> 64 blocks x 256 threads
    feat_kernel<<<64, 256>>>(feature_emb, W, b);

    // Kernel B: 65536 warps -> 8192 blocks x 256 threads (8 warps/block)
    edge_head_kernel<<<BS / 8, 256>>>(node_emb, W, out);
}